// round 4
// baseline (speedup 1.0000x reference)
#include <cuda_runtime.h>
#include <cuda_bf16.h>

#define BATCH     8192
#define IN_CAP_SZ 5
#define IN_CAP_N  1152
#define OUT_CAP_N 55
#define F4_PER_K  288    // 1152/4 float4 per (b,i) row
#define F4_PER_B  1440   // 5*288 float4 per batch element

// 16 CTAs/SM * 128 thr => <=32 regs/thread => all 2048 CTAs resident (one wave)
__global__ __launch_bounds__(128, 16) void digitcaps_kernel(
    const float4* __restrict__ u4,   // (B, 5, 1152) as float4
    const float4* __restrict__ w4,   // (1152,) as float4
    const float*  __restrict__ bvec, // (55,)
    float*        __restrict__ out)  // (B, 55)
{
    __shared__ float4 ws[F4_PER_K];
    const int tid = threadIdx.x;
    for (int idx = tid; idx < F4_PER_K; idx += 128)
        ws[idx] = w4[idx];
    __syncthreads();

    const int lane = tid & 31;
    const int warp = tid >> 5;
    const int b    = blockIdx.x * 4 + warp;   // grid=2048, 4 warps/block -> 8192

    // ---- Phase 1: uh[i] = sum_k u[b,i,k]*W[k]; 5 independent load+FMA streams ----
    const float4* up = u4 + (size_t)b * F4_PER_B + lane;

    float acc[5] = {0.f, 0.f, 0.f, 0.f, 0.f};
    #pragma unroll
    for (int j = 0; j < 9; j++) {
        const float4 w  = ws[j * 32 + lane];
        const float4 x0 = __ldcs(&up[0 * F4_PER_K + j * 32]);
        const float4 x1 = __ldcs(&up[1 * F4_PER_K + j * 32]);
        const float4 x2 = __ldcs(&up[2 * F4_PER_K + j * 32]);
        const float4 x3 = __ldcs(&up[3 * F4_PER_K + j * 32]);
        const float4 x4 = __ldcs(&up[4 * F4_PER_K + j * 32]);
        acc[0] = fmaf(x0.x, w.x, fmaf(x0.y, w.y, fmaf(x0.z, w.z, fmaf(x0.w, w.w, acc[0]))));
        acc[1] = fmaf(x1.x, w.x, fmaf(x1.y, w.y, fmaf(x1.z, w.z, fmaf(x1.w, w.w, acc[1]))));
        acc[2] = fmaf(x2.x, w.x, fmaf(x2.y, w.y, fmaf(x2.z, w.z, fmaf(x2.w, w.w, acc[2]))));
        acc[3] = fmaf(x3.x, w.x, fmaf(x3.y, w.y, fmaf(x3.z, w.z, fmaf(x3.w, w.w, acc[3]))));
        acc[4] = fmaf(x4.x, w.x, fmaf(x4.y, w.y, fmaf(x4.z, w.z, fmaf(x4.w, w.w, acc[4]))));
    }

    // 5 interleaved butterfly reductions -> all lanes hold uh[i]
    #pragma unroll
    for (int off = 16; off > 0; off >>= 1) {
        #pragma unroll
        for (int i = 0; i < 5; i++)
            acc[i] += __shfl_xor_sync(0xffffffffu, acc[i], off);
    }

    // ---- Phase 2: routing. Lane owns out-capsules o0=lane, o1=lane+32. ----
    const int  o0   = lane;
    const int  o1   = lane + 32;
    const bool has1 = (o1 < OUT_CAP_N);

    const float base0 = bvec[o0];
    const float base1 = has1 ? bvec[o1] : 0.f;

    // Iteration 0: b_ij is i-independent => one softmax; s_o = c_o * sum_i uh_i.
    float m = has1 ? fmaxf(base0, base1) : base0;
    #pragma unroll
    for (int off = 16; off > 0; off >>= 1)
        m = fmaxf(m, __shfl_xor_sync(0xffffffffu, m, off));

    const float e0 = __expf(base0 - m);
    const float e1 = has1 ? __expf(base1 - m) : 0.f;
    float d = e0 + e1;
    #pragma unroll
    for (int off = 16; off > 0; off >>= 1)
        d += __shfl_xor_sync(0xffffffffu, d, off);

    const float sumUh = acc[0] + acc[1] + acc[2] + acc[3] + acc[4];
    const float r0    = __fdividef(sumUh, d);
    const float s0    = e0 * r0;
    const float s1    = e1 * r0;
    // squash (OUT_CAP_SZ=1): v = |s|/(1+s^2) * s
    const float v0 = __fdividef(fabsf(s0) * s0, 1.f + s0 * s0);
    const float v1 = __fdividef(fabsf(s1) * s1, 1.f + s1 * s1);

    // Iteration 1 (final): b_ij(o,i) = base_o + v_o*uh_i.
    // Register diet: keep only mi[5] and di[5] live; recompute exps later.
    float mi[5];
    #pragma unroll
    for (int i = 0; i < 5; i++) {
        mi[i] = fmaf(v0, acc[i], base0);
        if (has1) mi[i] = fmaxf(mi[i], fmaf(v1, acc[i], base1));
    }
    #pragma unroll
    for (int off = 16; off > 0; off >>= 1) {
        #pragma unroll
        for (int i = 0; i < 5; i++)
            mi[i] = fmaxf(mi[i], __shfl_xor_sync(0xffffffffu, mi[i], off));
    }

    float di[5];
    #pragma unroll
    for (int i = 0; i < 5; i++) {
        const float a0 = __expf(fmaf(v0, acc[i], base0) - mi[i]);
        const float a1 = has1 ? __expf(fmaf(v1, acc[i], base1) - mi[i]) : 0.f;
        di[i] = a0 + a1;
    }
    #pragma unroll
    for (int off = 16; off > 0; off >>= 1) {
        #pragma unroll
        for (int i = 0; i < 5; i++)
            di[i] += __shfl_xor_sync(0xffffffffu, di[i], off);
    }

    float t0 = 0.f, t1 = 0.f;
    #pragma unroll
    for (int i = 0; i < 5; i++) {
        const float r  = __fdividef(acc[i], di[i]);
        const float a0 = __expf(fmaf(v0, acc[i], base0) - mi[i]);   // recompute
        t0 = fmaf(a0, r, t0);
        if (has1) {
            const float a1 = __expf(fmaf(v1, acc[i], base1) - mi[i]);
            t1 = fmaf(a1, r, t1);
        }
    }
    const float w0 = __fdividef(fabsf(t0) * t0, 1.f + t0 * t0);

    out[(size_t)b * OUT_CAP_N + o0] = w0;
    if (has1) {
        const float w1 = __fdividef(fabsf(t1) * t1, 1.f + t1 * t1);
        out[(size_t)b * OUT_CAP_N + o1] = w1;
    }
}

extern "C" void kernel_launch(void* const* d_in, const int* in_sizes, int n_in,
                              void* d_out, int out_size) {
    const float4* u4   = (const float4*)d_in[0];  // (8192,5,128,3,3) f32
    const float4* w4   = (const float4*)d_in[1];  // (1,1152,1) f32
    const float*  bvec = (const float*) d_in[2];  // (55,1) f32
    float*        out  = (float*)d_out;           // (8192,55,1) f32

    digitcaps_kernel<<<BATCH / 4, 128>>>(u4, w4, bvec, out);
}

// round 5
// speedup vs baseline: 1.0502x; 1.0502x over previous
#include <cuda_runtime.h>
#include <cuda_bf16.h>

#define BATCH     8192
#define IN_CAP_SZ 5
#define IN_CAP_N  1152
#define OUT_CAP_N 55
#define F4_PER_K  288    // 1152/4 float4 per (b,i) row
#define F4_PER_B  1440   // 5*288 float4 per batch element

// Half-warp per batch element: lanes 0-15 -> element 2w, lanes 16-31 -> 2w+1.
// grid=1024 CTAs, ~50 regs -> 10 CTAs/SM -> entire grid resident in ONE wave.
__global__ __launch_bounds__(128) void digitcaps_kernel(
    const float4* __restrict__ u4,   // (B, 5, 1152) as float4
    const float4* __restrict__ w4,   // (1152,) as float4
    const float*  __restrict__ bvec, // (55,)
    float*        __restrict__ out)  // (B, 55)
{
    __shared__ float4 ws[F4_PER_K];
    const int tid = threadIdx.x;
    for (int idx = tid; idx < F4_PER_K; idx += 128)
        ws[idx] = w4[idx];
    __syncthreads();

    const int lane   = tid & 31;
    const int warp   = tid >> 5;
    const int lane16 = lane & 15;
    const int half   = lane >> 4;
    const int b      = blockIdx.x * 8 + warp * 2 + half;  // grid=1024 -> 8192 elems

    // ---- Phase 1: uh[i] = sum_k u[b,i,k]*W[k]; 5 streams, 18 steps of 16 lanes ----
    const float4* up = u4 + (size_t)b * F4_PER_B + lane16;

    float acc[5] = {0.f, 0.f, 0.f, 0.f, 0.f};
    #pragma unroll
    for (int j = 0; j < 18; j++) {
        const float4 w  = ws[j * 16 + lane16];
        const float4 x0 = up[0 * F4_PER_K + j * 16];
        const float4 x1 = up[1 * F4_PER_K + j * 16];
        const float4 x2 = up[2 * F4_PER_K + j * 16];
        const float4 x3 = up[3 * F4_PER_K + j * 16];
        const float4 x4 = up[4 * F4_PER_K + j * 16];
        acc[0] = fmaf(x0.x, w.x, fmaf(x0.y, w.y, fmaf(x0.z, w.z, fmaf(x0.w, w.w, acc[0]))));
        acc[1] = fmaf(x1.x, w.x, fmaf(x1.y, w.y, fmaf(x1.z, w.z, fmaf(x1.w, w.w, acc[1]))));
        acc[2] = fmaf(x2.x, w.x, fmaf(x2.y, w.y, fmaf(x2.z, w.z, fmaf(x2.w, w.w, acc[2]))));
        acc[3] = fmaf(x3.x, w.x, fmaf(x3.y, w.y, fmaf(x3.z, w.z, fmaf(x3.w, w.w, acc[3]))));
        acc[4] = fmaf(x4.x, w.x, fmaf(x4.y, w.y, fmaf(x4.z, w.z, fmaf(x4.w, w.w, acc[4]))));
    }

    // 5 interleaved butterfly reductions over the 16-lane half (offsets 8..1
    // never cross the half boundary)
    #pragma unroll
    for (int off = 8; off > 0; off >>= 1) {
        #pragma unroll
        for (int i = 0; i < 5; i++)
            acc[i] += __shfl_xor_sync(0xffffffffu, acc[i], off);
    }
    // all 16 lanes of this half now hold uh[i] = acc[i]

    // ---- Phase 2: routing. Lane owns out-capsules o_q = lane16 + 16q, q=0..3 ----
    float base[4];
    bool  valid[4];
    #pragma unroll
    for (int q = 0; q < 4; q++) {
        const int o = lane16 + 16 * q;
        valid[q] = (o < OUT_CAP_N);
        base[q]  = valid[q] ? bvec[o] : -1e30f;
    }

    // Iteration 0: b_ij is i-independent => one softmax; s_o = c_o * sum_i uh_i.
    float m = fmaxf(fmaxf(base[0], base[1]), fmaxf(base[2], base[3]));
    #pragma unroll
    for (int off = 8; off > 0; off >>= 1)
        m = fmaxf(m, __shfl_xor_sync(0xffffffffu, m, off));

    float e[4], d = 0.f;
    #pragma unroll
    for (int q = 0; q < 4; q++) {
        e[q] = valid[q] ? __expf(base[q] - m) : 0.f;
        d += e[q];
    }
    #pragma unroll
    for (int off = 8; off > 0; off >>= 1)
        d += __shfl_xor_sync(0xffffffffu, d, off);

    const float sumUh = acc[0] + acc[1] + acc[2] + acc[3] + acc[4];
    const float r0    = __fdividef(sumUh, d);

    float v[4];
    #pragma unroll
    for (int q = 0; q < 4; q++) {
        const float s = e[q] * r0;
        v[q] = __fdividef(fabsf(s) * s, 1.f + s * s);   // squash, OUT_CAP_SZ=1
    }

    // Iteration 1 (final): b_ij(o,i) = base_o + v_o*uh_i; 5 interleaved softmaxes.
    float mi[5];
    #pragma unroll
    for (int i = 0; i < 5; i++) {
        float lm = -1e30f;
        #pragma unroll
        for (int q = 0; q < 4; q++)
            if (valid[q]) lm = fmaxf(lm, fmaf(v[q], acc[i], base[q]));
        mi[i] = lm;
    }
    #pragma unroll
    for (int off = 8; off > 0; off >>= 1) {
        #pragma unroll
        for (int i = 0; i < 5; i++)
            mi[i] = fmaxf(mi[i], __shfl_xor_sync(0xffffffffu, mi[i], off));
    }

    float di[5];
    #pragma unroll
    for (int i = 0; i < 5; i++) {
        float ld = 0.f;
        #pragma unroll
        for (int q = 0; q < 4; q++)
            if (valid[q]) ld += __expf(fmaf(v[q], acc[i], base[q]) - mi[i]);
        di[i] = ld;
    }
    #pragma unroll
    for (int off = 8; off > 0; off >>= 1) {
        #pragma unroll
        for (int i = 0; i < 5; i++)
            di[i] += __shfl_xor_sync(0xffffffffu, di[i], off);
    }

    float t[4] = {0.f, 0.f, 0.f, 0.f};
    #pragma unroll
    for (int i = 0; i < 5; i++) {
        const float r = __fdividef(acc[i], di[i]);
        #pragma unroll
        for (int q = 0; q < 4; q++)
            if (valid[q])
                t[q] = fmaf(__expf(fmaf(v[q], acc[i], base[q]) - mi[i]), r, t[q]);
    }

    #pragma unroll
    for (int q = 0; q < 4; q++) {
        if (valid[q]) {
            const float wq = __fdividef(fabsf(t[q]) * t[q], 1.f + t[q] * t[q]);
            out[(size_t)b * OUT_CAP_N + lane16 + 16 * q] = wq;
        }
    }
}

extern "C" void kernel_launch(void* const* d_in, const int* in_sizes, int n_in,
                              void* d_out, int out_size) {
    const float4* u4   = (const float4*)d_in[0];  // (8192,5,128,3,3) f32
    const float4* w4   = (const float4*)d_in[1];  // (1,1152,1) f32
    const float*  bvec = (const float*) d_in[2];  // (55,1) f32
    float*        out  = (float*)d_out;           // (8192,55,1) f32

    digitcaps_kernel<<<BATCH / 8, 128>>>(u4, w4, bvec, out);
}

// round 7
// speedup vs baseline: 1.0730x; 1.0217x over previous
#include <cuda_runtime.h>
#include <cuda_bf16.h>
#include <cstdint>

#define BATCH      8192
#define IN_CAP_N   1152
#define OUT_CAP_N  55
#define F4_PER_K   288            // 1152/4 float4 per (b,i) row
#define F4_PER_B   1440           // 5*288 float4 per batch element
#define ELEM_BYTES 23040          // 1440 * 16
#define NBUF       2
#define ELEMS_PER_WARP 16
#define WARPS      4
#define DYN_SMEM   (WARPS * NBUF * ELEM_BYTES)   // 184320 B

__device__ __forceinline__ uint32_t smem_u32(const void* p) {
    uint32_t a;
    asm("{ .reg .u64 t; cvta.to.shared.u64 t, %1; cvt.u32.u64 %0, t; }"
        : "=r"(a) : "l"(p));
    return a;
}
__device__ __forceinline__ void mbar_init(uint32_t mbar, uint32_t cnt) {
    asm volatile("mbarrier.init.shared.b64 [%0], %1;" :: "r"(mbar), "r"(cnt) : "memory");
}
__device__ __forceinline__ void mbar_expect_tx(uint32_t mbar, uint32_t bytes) {
    asm volatile("mbarrier.arrive.expect_tx.shared.b64 _, [%0], %1;"
                 :: "r"(mbar), "r"(bytes) : "memory");
}
__device__ __forceinline__ void mbar_wait(uint32_t mbar, uint32_t parity) {
    asm volatile(
        "{\n\t.reg .pred P;\n\t"
        "WL_%=:\n\t"
        "mbarrier.try_wait.parity.acquire.cta.shared::cta.b64 P, [%0], %1, 0x989680;\n\t"
        "@P bra WD_%=;\n\t"
        "bra WL_%=;\n\t"
        "WD_%=:\n\t}"
        :: "r"(mbar), "r"(parity) : "memory");
}
__device__ __forceinline__ void bulk_load(uint32_t dst_smem, const void* src_gmem,
                                          uint32_t bytes, uint32_t mbar) {
    asm volatile(
        "cp.async.bulk.shared::cta.global.mbarrier::complete_tx::bytes [%0], [%1], %2, [%3];"
        :: "r"(dst_smem), "l"(src_gmem), "r"(bytes), "r"(mbar) : "memory");
}

__global__ __launch_bounds__(128, 1) void digitcaps_kernel(
    const float4* __restrict__ u4,   // (B, 5, 1152) as float4
    const float4* __restrict__ w4,   // (1152,) as float4
    const float*  __restrict__ bvec, // (55,)
    float*        __restrict__ out)  // (B, 55)
{
    extern __shared__ __align__(1024) unsigned char dynbuf[];   // 4 warps * 2 * 23040
    __shared__ float4 ws[F4_PER_K];
    __shared__ __align__(8) unsigned long long mbar_store[WARPS * NBUF];

    const int tid  = threadIdx.x;
    const int lane = tid & 31;
    const int warp = tid >> 5;

    for (int idx = tid; idx < F4_PER_K; idx += 128)
        ws[idx] = w4[idx];
    if (tid < WARPS * NBUF)
        mbar_init(smem_u32(&mbar_store[tid]), 1);
    __syncthreads();

    const int    gw = blockIdx.x * WARPS + warp;            // 0..511 warp-streams
    const size_t e0 = (size_t)gw * ELEMS_PER_WARP;          // first element of stream
    unsigned char* mybuf  = dynbuf + (size_t)warp * (NBUF * ELEM_BYTES);
    const uint32_t buf_u  = smem_u32(mybuf);
    const uint32_t mb_u   = smem_u32(&mbar_store[warp * NBUF]);
    const char*    src0   = (const char*)u4 + e0 * (size_t)ELEM_BYTES;

    // Prologue: fill both buffers
    if (lane == 0) {
        #pragma unroll
        for (int s = 0; s < NBUF; s++) {
            mbar_expect_tx(mb_u + s * 8, ELEM_BYTES);
            bulk_load(buf_u + s * ELEM_BYTES, src0 + (size_t)s * ELEM_BYTES,
                      ELEM_BYTES, mb_u + s * 8);
        }
    }

    // Routing-invariant epilogue constants
    const int  o0   = lane;
    const int  o1   = lane + 32;
    const bool has1 = (o1 < OUT_CAP_N);
    const float base0 = bvec[o0];
    const float base1 = has1 ? bvec[o1] : 0.f;

    // Iteration-0 softmax depends only on bvec: hoist out of the element loop.
    float m0 = has1 ? fmaxf(base0, base1) : base0;
    #pragma unroll
    for (int off = 16; off > 0; off >>= 1)
        m0 = fmaxf(m0, __shfl_xor_sync(0xffffffffu, m0, off));
    const float e0w = __expf(base0 - m0);
    const float e1w = has1 ? __expf(base1 - m0) : 0.f;
    float d0 = e0w + e1w;
    #pragma unroll
    for (int off = 16; off > 0; off >>= 1)
        d0 += __shfl_xor_sync(0xffffffffu, d0, off);

    for (int n = 0; n < ELEMS_PER_WARP; n++) {
        const int s  = n & 1;
        const int ph = (n >> 1) & 1;
        mbar_wait(mb_u + s * 8, (uint32_t)ph);

        // ---- Phase 1 from smem: 5 streams, 9 steps ----
        const float4* ub = (const float4*)(mybuf + s * ELEM_BYTES);
        float acc[5] = {0.f, 0.f, 0.f, 0.f, 0.f};
        #pragma unroll
        for (int j = 0; j < 9; j++) {
            const float4 w  = ws[j * 32 + lane];
            const float4 x0 = ub[0 * F4_PER_K + j * 32 + lane];
            const float4 x1 = ub[1 * F4_PER_K + j * 32 + lane];
            const float4 x2 = ub[2 * F4_PER_K + j * 32 + lane];
            const float4 x3 = ub[3 * F4_PER_K + j * 32 + lane];
            const float4 x4 = ub[4 * F4_PER_K + j * 32 + lane];
            acc[0] = fmaf(x0.x, w.x, fmaf(x0.y, w.y, fmaf(x0.z, w.z, fmaf(x0.w, w.w, acc[0]))));
            acc[1] = fmaf(x1.x, w.x, fmaf(x1.y, w.y, fmaf(x1.z, w.z, fmaf(x1.w, w.w, acc[1]))));
            acc[2] = fmaf(x2.x, w.x, fmaf(x2.y, w.y, fmaf(x2.z, w.z, fmaf(x2.w, w.w, acc[2]))));
            acc[3] = fmaf(x3.x, w.x, fmaf(x3.y, w.y, fmaf(x3.z, w.z, fmaf(x3.w, w.w, acc[3]))));
            acc[4] = fmaf(x4.x, w.x, fmaf(x4.y, w.y, fmaf(x4.z, w.z, fmaf(x4.w, w.w, acc[4]))));
        }

        // All lanes have consumed the buffer (their FMAs read every loaded value);
        // sync the warp, then recycle the slot with the element-after-next.
        __syncwarp();
        if (lane == 0 && n + NBUF < ELEMS_PER_WARP) {
            mbar_expect_tx(mb_u + s * 8, ELEM_BYTES);
            bulk_load(buf_u + s * ELEM_BYTES,
                      src0 + (size_t)(n + NBUF) * ELEM_BYTES,
                      ELEM_BYTES, mb_u + s * 8);
        }

        // 5 interleaved butterfly reductions -> all lanes hold uh[i]
        #pragma unroll
        for (int off = 16; off > 0; off >>= 1) {
            #pragma unroll
            for (int i = 0; i < 5; i++)
                acc[i] += __shfl_xor_sync(0xffffffffu, acc[i], off);
        }

        // ---- Phase 2: routing (overlaps with the in-flight TMA) ----
        const float sumUh = acc[0] + acc[1] + acc[2] + acc[3] + acc[4];
        const float r0    = __fdividef(sumUh, d0);
        const float s0    = e0w * r0;
        const float s1    = e1w * r0;
        const float v0 = __fdividef(fabsf(s0) * s0, 1.f + s0 * s0);  // squash
        const float v1 = __fdividef(fabsf(s1) * s1, 1.f + s1 * s1);

        float mi[5];
        #pragma unroll
        for (int i = 0; i < 5; i++) {
            mi[i] = fmaf(v0, acc[i], base0);
            if (has1) mi[i] = fmaxf(mi[i], fmaf(v1, acc[i], base1));
        }
        #pragma unroll
        for (int off = 16; off > 0; off >>= 1) {
            #pragma unroll
            for (int i = 0; i < 5; i++)
                mi[i] = fmaxf(mi[i], __shfl_xor_sync(0xffffffffu, mi[i], off));
        }

        float e0i[5], e1i[5], di[5];
        #pragma unroll
        for (int i = 0; i < 5; i++) {
            e0i[i] = __expf(fmaf(v0, acc[i], base0) - mi[i]);
            e1i[i] = has1 ? __expf(fmaf(v1, acc[i], base1) - mi[i]) : 0.f;
            di[i]  = e0i[i] + e1i[i];
        }
        #pragma unroll
        for (int off = 16; off > 0; off >>= 1) {
            #pragma unroll
            for (int i = 0; i < 5; i++)
                di[i] += __shfl_xor_sync(0xffffffffu, di[i], off);
        }

        float t0 = 0.f, t1 = 0.f;
        #pragma unroll
        for (int i = 0; i < 5; i++) {
            const float r = __fdividef(acc[i], di[i]);
            t0 = fmaf(e0i[i], r, t0);
            t1 = fmaf(e1i[i], r, t1);
        }
        const float w0 = __fdividef(fabsf(t0) * t0, 1.f + t0 * t0);
        const size_t b = e0 + (size_t)n;
        out[b * OUT_CAP_N + o0] = w0;
        if (has1) {
            const float w1 = __fdividef(fabsf(t1) * t1, 1.f + t1 * t1);
            out[b * OUT_CAP_N + o1] = w1;
        }
    }
}

extern "C" void kernel_launch(void* const* d_in, const int* in_sizes, int n_in,
                              void* d_out, int out_size) {
    const float4* u4   = (const float4*)d_in[0];  // (8192,5,128,3,3) f32
    const float4* w4   = (const float4*)d_in[1];  // (1,1152,1) f32
    const float*  bvec = (const float*) d_in[2];  // (55,1) f32
    float*        out  = (float*)d_out;           // (8192,55,1) f32

    static int smem_set = 0;
    if (!smem_set) {
        cudaFuncSetAttribute(digitcaps_kernel,
                             cudaFuncAttributeMaxDynamicSharedMemorySize, DYN_SMEM);
        smem_set = 1;
    }
    // 128 CTAs * 4 warps * 16 elements = 8192
    digitcaps_kernel<<<128, 128, DYN_SMEM>>>(u4, w4, bvec, out);
}

// round 8
// speedup vs baseline: 1.1106x; 1.0351x over previous
#include <cuda_runtime.h>
#include <cuda_bf16.h>
#include <cstdint>

#define BATCH      8192
#define IN_CAP_N   1152
#define OUT_CAP_N  55
#define F4_PER_K   288            // 1152/4 float4 per (b,i) row
#define F4_PER_B   1440           // 5*288 float4 per batch element
#define ELEM_BYTES 23040          // 1440 * 16
#define WARPS      8
#define NSTREAM    (148 * WARPS)  // 1184 warp-streams, persistent-strided
#define DYN_SMEM   (WARPS * ELEM_BYTES)   // 184320 B, 1 CTA/SM

__device__ __forceinline__ uint32_t smem_u32(const void* p) {
    uint32_t a;
    asm("{ .reg .u64 t; cvta.to.shared.u64 t, %1; cvt.u32.u64 %0, t; }"
        : "=r"(a) : "l"(p));
    return a;
}
__device__ __forceinline__ void mbar_init(uint32_t mbar, uint32_t cnt) {
    asm volatile("mbarrier.init.shared.b64 [%0], %1;" :: "r"(mbar), "r"(cnt) : "memory");
}
__device__ __forceinline__ void mbar_expect_tx(uint32_t mbar, uint32_t bytes) {
    asm volatile("mbarrier.arrive.expect_tx.shared.b64 _, [%0], %1;"
                 :: "r"(mbar), "r"(bytes) : "memory");
}
__device__ __forceinline__ void mbar_wait(uint32_t mbar, uint32_t parity) {
    asm volatile(
        "{\n\t.reg .pred P;\n\t"
        "WL_%=:\n\t"
        "mbarrier.try_wait.parity.acquire.cta.shared::cta.b64 P, [%0], %1, 0x989680;\n\t"
        "@P bra WD_%=;\n\t"
        "bra WL_%=;\n\t"
        "WD_%=:\n\t}"
        :: "r"(mbar), "r"(parity) : "memory");
}
__device__ __forceinline__ void bulk_load(uint32_t dst_smem, const void* src_gmem,
                                          uint32_t bytes, uint32_t mbar) {
    asm volatile(
        "cp.async.bulk.shared::cta.global.mbarrier::complete_tx::bytes [%0], [%1], %2, [%3];"
        :: "r"(dst_smem), "l"(src_gmem), "r"(bytes), "r"(mbar) : "memory");
}

__global__ __launch_bounds__(256, 1) void digitcaps_kernel(
    const float4* __restrict__ u4,   // (B, 5, 1152) as float4
    const float4* __restrict__ w4,   // (1152,) as float4
    const float*  __restrict__ bvec, // (55,)
    float*        __restrict__ out)  // (B, 55)
{
    extern __shared__ __align__(1024) unsigned char dynbuf[];   // 8 warps * 23040
    __shared__ float4 ws[F4_PER_K];
    __shared__ __align__(8) unsigned long long mbar_store[WARPS];

    const int tid  = threadIdx.x;
    const int lane = tid & 31;
    const int warp = tid >> 5;

    for (int idx = tid; idx < F4_PER_K; idx += 256)
        ws[idx] = w4[idx];
    if (tid < WARPS)
        mbar_init(smem_u32(&mbar_store[tid]), 1);
    __syncthreads();

    const int gw = blockIdx.x * WARPS + warp;   // 0..1183 warp-stream id
    unsigned char* mybuf = dynbuf + (size_t)warp * ELEM_BYTES;
    const uint32_t buf_u = smem_u32(mybuf);
    const uint32_t mb_u  = smem_u32(&mbar_store[warp]);
    const char*    usrc  = (const char*)u4;

    // Prologue: load first element of this stream
    if (lane == 0 && gw < BATCH) {
        mbar_expect_tx(mb_u, ELEM_BYTES);
        bulk_load(buf_u, usrc + (size_t)gw * ELEM_BYTES, ELEM_BYTES, mb_u);
    }

    // Routing-invariant epilogue constants
    const int  o0   = lane;
    const int  o1   = lane + 32;
    const bool has1 = (o1 < OUT_CAP_N);
    const float base0 = bvec[o0];
    const float base1 = has1 ? bvec[o1] : 0.f;

    // Iteration-0 softmax depends only on bvec: hoist out of the element loop.
    float m0 = has1 ? fmaxf(base0, base1) : base0;
    #pragma unroll
    for (int off = 16; off > 0; off >>= 1)
        m0 = fmaxf(m0, __shfl_xor_sync(0xffffffffu, m0, off));
    const float e0w = __expf(base0 - m0);
    const float e1w = has1 ? __expf(base1 - m0) : 0.f;
    float d0 = e0w + e1w;
    #pragma unroll
    for (int off = 16; off > 0; off >>= 1)
        d0 += __shfl_xor_sync(0xffffffffu, d0, off);

    int k = 0;
    for (int n = gw; n < BATCH; n += NSTREAM, k++) {
        mbar_wait(mb_u, (uint32_t)(k & 1));

        // ---- Phase 1 from smem: 5 streams, 9 steps ----
        const float4* ub = (const float4*)mybuf;
        float acc[5] = {0.f, 0.f, 0.f, 0.f, 0.f};
        #pragma unroll
        for (int j = 0; j < 9; j++) {
            const float4 w  = ws[j * 32 + lane];
            const float4 x0 = ub[0 * F4_PER_K + j * 32 + lane];
            const float4 x1 = ub[1 * F4_PER_K + j * 32 + lane];
            const float4 x2 = ub[2 * F4_PER_K + j * 32 + lane];
            const float4 x3 = ub[3 * F4_PER_K + j * 32 + lane];
            const float4 x4 = ub[4 * F4_PER_K + j * 32 + lane];
            acc[0] = fmaf(x0.x, w.x, fmaf(x0.y, w.y, fmaf(x0.z, w.z, fmaf(x0.w, w.w, acc[0]))));
            acc[1] = fmaf(x1.x, w.x, fmaf(x1.y, w.y, fmaf(x1.z, w.z, fmaf(x1.w, w.w, acc[1]))));
            acc[2] = fmaf(x2.x, w.x, fmaf(x2.y, w.y, fmaf(x2.z, w.z, fmaf(x2.w, w.w, acc[2]))));
            acc[3] = fmaf(x3.x, w.x, fmaf(x3.y, w.y, fmaf(x3.z, w.z, fmaf(x3.w, w.w, acc[3]))));
            acc[4] = fmaf(x4.x, w.x, fmaf(x4.y, w.y, fmaf(x4.z, w.z, fmaf(x4.w, w.w, acc[4]))));
        }

        // All lanes consumed the slot (FMAs read every value); recycle with
        // this stream's next element. Epilogue below overlaps the new load.
        __syncwarp();
        if (lane == 0 && n + NSTREAM < BATCH) {
            mbar_expect_tx(mb_u, ELEM_BYTES);
            bulk_load(buf_u, usrc + (size_t)(n + NSTREAM) * ELEM_BYTES,
                      ELEM_BYTES, mb_u);
        }

        // 5 interleaved butterfly reductions -> all lanes hold uh[i]
        #pragma unroll
        for (int off = 16; off > 0; off >>= 1) {
            #pragma unroll
            for (int i = 0; i < 5; i++)
                acc[i] += __shfl_xor_sync(0xffffffffu, acc[i], off);
        }

        // ---- Phase 2: routing ----
        const float sumUh = acc[0] + acc[1] + acc[2] + acc[3] + acc[4];
        const float r0    = __fdividef(sumUh, d0);
        const float s0    = e0w * r0;
        const float s1    = e1w * r0;
        const float v0 = __fdividef(fabsf(s0) * s0, 1.f + s0 * s0);  // squash
        const float v1 = __fdividef(fabsf(s1) * s1, 1.f + s1 * s1);

        float mi[5];
        #pragma unroll
        for (int i = 0; i < 5; i++) {
            mi[i] = fmaf(v0, acc[i], base0);
            if (has1) mi[i] = fmaxf(mi[i], fmaf(v1, acc[i], base1));
        }
        #pragma unroll
        for (int off = 16; off > 0; off >>= 1) {
            #pragma unroll
            for (int i = 0; i < 5; i++)
                mi[i] = fmaxf(mi[i], __shfl_xor_sync(0xffffffffu, mi[i], off));
        }

        float e0i[5], e1i[5], di[5];
        #pragma unroll
        for (int i = 0; i < 5; i++) {
            e0i[i] = __expf(fmaf(v0, acc[i], base0) - mi[i]);
            e1i[i] = has1 ? __expf(fmaf(v1, acc[i], base1) - mi[i]) : 0.f;
            di[i]  = e0i[i] + e1i[i];
        }
        #pragma unroll
        for (int off = 16; off > 0; off >>= 1) {
            #pragma unroll
            for (int i = 0; i < 5; i++)
                di[i] += __shfl_xor_sync(0xffffffffu, di[i], off);
        }

        float t0 = 0.f, t1 = 0.f;
        #pragma unroll
        for (int i = 0; i < 5; i++) {
            const float r = __fdividef(acc[i], di[i]);
            t0 = fmaf(e0i[i], r, t0);
            t1 = fmaf(e1i[i], r, t1);
        }
        const float w0 = __fdividef(fabsf(t0) * t0, 1.f + t0 * t0);
        out[(size_t)n * OUT_CAP_N + o0] = w0;
        if (has1) {
            const float w1 = __fdividef(fabsf(t1) * t1, 1.f + t1 * t1);
            out[(size_t)n * OUT_CAP_N + o1] = w1;
        }
    }
}

extern "C" void kernel_launch(void* const* d_in, const int* in_sizes, int n_in,
                              void* d_out, int out_size) {
    const float4* u4   = (const float4*)d_in[0];  // (8192,5,128,3,3) f32
    const float4* w4   = (const float4*)d_in[1];  // (1,1152,1) f32
    const float*  bvec = (const float*) d_in[2];  // (55,1) f32
    float*        out  = (float*)d_out;           // (8192,55,1) f32

    static int smem_set = 0;
    if (!smem_set) {
        cudaFuncSetAttribute(digitcaps_kernel,
                             cudaFuncAttributeMaxDynamicSharedMemorySize, DYN_SMEM);
        smem_set = 1;
    }
    // 148 persistent CTAs * 8 warp-streams, strided element assignment
    digitcaps_kernel<<<148, 256, DYN_SMEM>>>(u4, w4, bvec, out);
}